// round 9
// baseline (speedup 1.0000x reference)
#include <cuda_runtime.h>
#include <cstdint>
#include <math.h>

#define NNODES 87381
#define NLEAF  65536

// =================== scratch (device globals; no allocation) =================
// Tiled+swizzled layout for GEMM A operands (128-row x 16-col chunks):
//   float index(row,k) = (rowblk*NCH + chunk)*2048 + (s*128+m)*8
//                        + ((2*c4 + half) ^ ((m>>1)&6) ^ (s<<2))
//   chunk=k>>4, kk=k&15, s=kk>>3, c4=kk&3, half=(kk>>2)&1, m=row&127.
// XOR swizzle => conflict-free LDS.64 fragment loads AND conflict-free STS.32
// scatter when rounding A in-GEMM.
__device__ float g_X [88064u * 640];       // x-projections [i|u|o|f]
__device__ float g_H2[683u * 10 * 2048];   // tf32-rounded h, tiled+swizzled
__device__ float g_HS2[128u * 10 * 2048];  // tf32-rounded child-sum, tiled+swizzled
__device__ float g_C [NNODES * 150];       // cell states (exact fp32)
__device__ float g_P [16384u * 480];       // parent projections [i|u|o]
__device__ float g_F [65536u * 160];       // child f-projections
// B operands, fragment-row layout: [chunk][s][c4][col(640)][half] (rows of 1280)
__device__ float g_Wxp[19 * 10240];        // Wx packed, tf32-rounded, K pad 304
__device__ float g_Whp[10 * 10240];        // Wh packed, tf32-rounded, K pad 160
__device__ float g_Wh2[160 * 640];         // Wh plain [k][i|u|o|f] for small levels
__device__ float g_bx[640];
__device__ float g_bh[640];

// =================== helpers ==================================================
__device__ __forceinline__ float to_tf32(float x) {
    unsigned u;
    asm("cvt.rna.tf32.f32 %0, %1;" : "=r"(u) : "f"(x));
    return __uint_as_float(u);
}
__device__ __forceinline__ float sigf(float x) {
    return __fdividef(1.0f, 1.0f + __expf(-x));
}
__device__ __forceinline__ float tanh_fast(float x) {
    return __fdividef(2.0f, 1.0f + __expf(-2.0f * x)) - 1.0f;
}
// float position of h(row, j) in tiled H buffer (NCH = 10), swizzled
__device__ __forceinline__ size_t hpos(int row, int j) {
    int rb = row >> 7, m = row & 127;
    int chunk = j >> 4, kk = j & 15;
    int s = kk >> 3, c4 = kk & 3, half = (kk >> 2) & 1;
    int off = (s * 128 + m) * 8 + (((c4 << 1) + half) ^ ((m >> 1) & 6) ^ (s << 2));
    return ((size_t)(rb * 10 + chunk) << 11) + (size_t)off;
}
__device__ __forceinline__ void mma8(float* d, const unsigned* a, const unsigned* b) {
    asm volatile(
        "mma.sync.aligned.m16n8k8.row.col.f32.tf32.tf32.f32 "
        "{%0,%1,%2,%3}, {%4,%5,%6,%7}, {%8,%9}, {%0,%1,%2,%3};\n"
        : "+f"(d[0]), "+f"(d[1]), "+f"(d[2]), "+f"(d[3])
        : "r"(a[0]), "r"(a[1]), "r"(a[2]), "r"(a[3]), "r"(b[0]), "r"(b[1]));
}
__device__ __forceinline__ void cp16(uint32_t dst, const void* src) {
    asm volatile("cp.async.ca.shared.global [%0], [%1], 16;" :: "r"(dst), "l"(src));
}
#define CP_COMMIT() asm volatile("cp.async.commit_group;" ::: "memory")
#define CP_WAIT2()  asm volatile("cp.async.wait_group 2;" ::: "memory")

// =================== weight packing ==========================================
__global__ void pack_kernel(
    const float* Wix, const float* bix, const float* Wfx, const float* bfx,
    const float* Wux, const float* bux, const float* Wox, const float* box_,
    const float* Wih, const float* bih, const float* Wfh, const float* bfh,
    const float* Wuh, const float* buh, const float* Woh, const float* boh)
{
    const int T0 = 19 * 10240;          // Wxp
    const int T1 = T0 + 10 * 10240;     // Whp
    const int T2 = T1 + 160 * 640;      // Wh2
    const int T3 = T2 + 640;            // bx
    const int T4 = T3 + 640;            // bh
    for (int idx = blockIdx.x * blockDim.x + threadIdx.x; idx < T4;
         idx += gridDim.x * blockDim.x) {
        if (idx < T0) {
            int rowI = idx / 1280, w = idx % 1280;
            int col = w >> 1, half = w & 1;
            int chunk = rowI >> 3, rr = rowI & 7;
            int k = chunk * 16 + (rr >> 2) * 8 + half * 4 + (rr & 3);
            int m = col / 160, cc = col % 160;
            float v = 0.f;
            if (k < 300 && cc < 150) {
                const float* W = (m == 0) ? Wix : (m == 1) ? Wux : (m == 2) ? Wox : Wfx;
                v = W[k * 150 + cc];
            }
            g_Wxp[idx] = to_tf32(v);
        } else if (idx < T1) {
            int t = idx - T0;
            int rowI = t / 1280, w = t % 1280;
            int col = w >> 1, half = w & 1;
            int chunk = rowI >> 3, rr = rowI & 7;
            int k = chunk * 16 + (rr >> 2) * 8 + half * 4 + (rr & 3);
            int m = col / 160, cc = col % 160;
            float v = 0.f;
            if (k < 150 && cc < 150) {
                const float* W = (m == 0) ? Wih : (m == 1) ? Wuh : (m == 2) ? Woh : Wfh;
                v = W[k * 150 + cc];
            }
            g_Whp[t] = to_tf32(v);
        } else if (idx < T2) {
            int t = idx - T1;
            int k = t / 640, c = t % 640, m = c / 160, cc = c % 160;
            float v = 0.f;
            if (k < 150 && cc < 150) {
                const float* W = (m == 0) ? Wih : (m == 1) ? Wuh : (m == 2) ? Woh : Wfh;
                v = W[k * 150 + cc];
            }
            g_Wh2[t] = v;
        } else if (idx < T3) {
            int c = idx - T2, m = c / 160, cc = c % 160;
            float v = 0.f;
            if (cc < 150) {
                const float* b = (m == 0) ? bix : (m == 1) ? bux : (m == 2) ? box_ : bfx;
                v = b[cc];
            }
            g_bx[c] = v;
        } else {
            int c = idx - T3, m = c / 160, cc = c % 160;
            float v = 0.f;
            if (cc < 150) {
                const float* b = (m == 0) ? bih : (m == 1) ? buh : (m == 2) ? boh : bfh;
                v = b[cc];
            }
            g_bh[c] = v;
        }
    }
}

// =================== tf32 mma GEMM ============================================
// BM=128, BN=160, 3-stage, 256 thr = 8 warps (2m x 4n), warp tile 64x40.
// grid = (ncolblk, nrowblk)  [colblk on x for A L2 reuse]
// ATILED:  A pre-tiled+swizzled (cp.async), lda_nch = #chunks per row-block.
// !ATILED: A = raw fp32 rows (lda_nch = lda); LDG.128 + cvt.rna + swizzled STS.
template<bool ATILED, bool BIAS>
__global__ __launch_bounds__(256, 2)
void gemm_tf32(const float* __restrict__ A, int lda_nch, int M,
               const float* __restrict__ Bp, int col0,
               float* __restrict__ C, int ldc,
               const float* __restrict__ bias, int nchunk, int Kreal)
{
    extern __shared__ __align__(16) float sm[];
    const uint32_t sbase = (uint32_t)__cvta_generic_to_shared(sm);

    const int tid    = threadIdx.x;
    const int lane   = tid & 31;
    const int wid    = tid >> 5;
    const int m_warp = (wid >> 2) * 64;
    const int n_warp = (wid & 3) * 40;
    const int colblk = blockIdx.x * 160;
    const int m0     = blockIdx.y * 128;
    const int bcol0  = col0 + colblk;
    const int c4     = lane & 3;
    const int q      = lane >> 2;

    float acc[4][5][4];
#pragma unroll
    for (int i = 0; i < 4; i++)
#pragma unroll
        for (int j = 0; j < 5; j++)
#pragma unroll
            for (int p = 0; p < 4; p++) acc[i][j][p] = 0.0f;

    float4 areg[2];

    auto ldgA = [&](int ch) {
        if (!ATILED && ch < nchunk) {
#pragma unroll
            for (int e = 0; e < 2; e++) {
                int id = tid + (e << 8);
                int r = id >> 2, slot = id & 3;
                int gr = m0 + r, gk = ch * 16 + slot * 4;
                float4 v = make_float4(0.f, 0.f, 0.f, 0.f);
                if (gr < M && gk < Kreal)
                    v = *(const float4*)(A + (size_t)gr * lda_nch + gk);
                areg[e] = v;
            }
        }
    };
    auto stsA = [&](int st, int ch) {
        if (!ATILED && ch < nchunk) {
            float* dst = sm + st * 4672;
#pragma unroll
            for (int e = 0; e < 2; e++) {
                int id = tid + (e << 8);
                int r = id >> 2, slot = id & 3;
                int s = slot >> 1, half = slot & 1;
                int xo = ((r >> 1) & 6) ^ (s << 2);
                float* base = dst + (s * 128 + r) * 8;
                float4 v = areg[e];
                base[(0 + half) ^ xo] = to_tf32(v.x);
                base[(2 + half) ^ xo] = to_tf32(v.y);
                base[(4 + half) ^ xo] = to_tf32(v.z);
                base[(6 + half) ^ xo] = to_tf32(v.w);
            }
        }
    };
    auto issue = [&](int st, int ch) {
        if (ch < nchunk) {
            const uint32_t dbase = sbase + st * 18688;
            if (ATILED) {
                const float* At = A + ((size_t)blockIdx.y * lda_nch + ch) * 2048;
                cp16(dbase + tid * 16, At + tid * 4);
                cp16(dbase + tid * 16 + 4096, At + tid * 4 + 1024);
            }
            const float* Bt = Bp + (size_t)ch * 10240 + (size_t)bcol0 * 2;
#pragma unroll
            for (int e = 0; e < 3; e++) {
                int id = tid + e * 256;
                if (id < 640) {
                    int r = id / 80, o = id - r * 80;
                    cp16(dbase + 8192 + r * 1312 + o * 16, Bt + r * 1280 + o * 4);
                }
            }
        }
        CP_COMMIT();
    };

    if (!ATILED) { ldgA(0); stsA(0, 0); ldgA(1); }
    issue(0, 0);
    issue(1, 1);
    issue(2, 2);

    int st = 0;
    for (int ch = 0; ch < nchunk; ch++) {
        CP_WAIT2();
        __syncthreads();
        const float* stf = sm + st * 4672;
        const float2* Af = (const float2*)stf;
        const float2* Bf = (const float2*)(stf + 2048);

#pragma unroll
        for (int s = 0; s < 2; s++) {
            const int xs = s << 1;
            unsigned a[4][4];
#pragma unroll
            for (int i = 0; i < 4; i++) {
                int m1 = m_warp + 16 * i + q;
                float2 lo = Af[(s * 128 + m1) * 4 + (c4 ^ ((m1 >> 2) & 3) ^ xs)];
                float2 hi = Af[(s * 128 + m1 + 8) * 4 + (c4 ^ (((m1 >> 2) + 2) & 3) ^ xs)];
                a[i][0] = __float_as_uint(lo.x);
                a[i][1] = __float_as_uint(hi.x);
                a[i][2] = __float_as_uint(lo.y);
                a[i][3] = __float_as_uint(hi.y);
            }
            unsigned b[5][2];
#pragma unroll
            for (int j = 0; j < 5; j++) {
                float2 bv = Bf[(s * 4 + c4) * 164 + n_warp + q + 8 * j];
                b[j][0] = __float_as_uint(bv.x);
                b[j][1] = __float_as_uint(bv.y);
            }
#pragma unroll
            for (int i = 0; i < 4; i++)
#pragma unroll
                for (int j = 0; j < 5; j++) mma8(acc[i][j], a[i], b[j]);
        }
        stsA((st == 2) ? 0 : st + 1, ch + 1);
        ldgA(ch + 2);
        __syncthreads();
        issue(st, ch + 3);
        st = (st == 2) ? 0 : st + 1;
    }

    const int r0 = m0 + m_warp + q;
    const int cl = n_warp + c4 * 2;
#pragma unroll
    for (int i = 0; i < 4; i++) {
#pragma unroll
        for (int h = 0; h < 2; h++) {
            int r = r0 + 16 * i + 8 * h;
            float* crow = C + (size_t)r * ldc + colblk;
#pragma unroll
            for (int j = 0; j < 5; j++) {
                int c = cl + 8 * j;
                float2 v = make_float2(acc[i][j][2 * h], acc[i][j][2 * h + 1]);
                if (BIAS) {
                    v.x += bias[bcol0 + c];
                    v.y += bias[bcol0 + c + 1];
                }
                *(float2*)(crow + c) = v;
            }
        }
    }
}

// =================== child-sum of h (tiled+swizzled, tf32) ====================
__global__ void hsum_kernel(int off_c, int n)
{
    int o2 = blockIdx.x * blockDim.x + threadIdx.x;     // logical float2 index
    const int TOT = (n >> 7) * 10 * 1024;
    if (o2 >= TOT) return;
    int w2 = o2 & 1023, t = o2 >> 10;
    int chunk = t % 10, rb = t / 10;
    int c4 = w2 & 3, pm = (w2 >> 2) & 127, s = w2 >> 9;
    int p = (rb << 7) + pm;
    const float2* H2 = (const float2*)g_H2;
    float2 a = make_float2(0.f, 0.f);
#pragma unroll
    for (int k = 0; k < 4; k++) {
        int crow = off_c + 4 * p + k;
        int cm = crow & 127;
        float2 hv = H2[((size_t)((crow >> 7) * 10 + chunk) << 10) +
                       (size_t)((s * 128 + cm) * 4 + (c4 ^ ((cm >> 2) & 3) ^ (s << 1)))];
        a.x += hv.x;
        a.y += hv.y;
    }
    a.x = to_tf32(a.x);
    a.y = to_tf32(a.y);
    ((float2*)g_HS2)[((size_t)(rb * 10 + chunk) << 10) +
                     (size_t)((s * 128 + pm) * 4 + (c4 ^ ((pm >> 2) & 3) ^ (s << 1)))] = a;
}

// =================== leaves (float2-vectorized) ================================
__global__ void leaf_kernel(float* __restrict__ out)
{
    int idx = blockIdx.x * blockDim.x + threadIdx.x;
    if (idx >= NLEAF * 80) return;
    int p = idx / 80, j2 = (idx - p * 80) * 2;
    if (j2 >= 150) {
        g_H2[hpos(p, j2)] = 0.0f;
        g_H2[hpos(p, j2 + 1)] = 0.0f;
        return;
    }
    const float* Xr = g_X + (size_t)p * 640;
    float2 xi = *(const float2*)(Xr + j2);
    float2 xu = *(const float2*)(Xr + 160 + j2);
    float2 xo = *(const float2*)(Xr + 320 + j2);
    float2 cv, hv;
    {
        float ig = sigf(xi.x + g_bh[j2]);
        float ug = tanh_fast(xu.x + g_bh[160 + j2]);
        float og = sigf(xo.x + g_bh[320 + j2]);
        cv.x = ig * ug;
        hv.x = og * tanh_fast(cv.x);
    }
    {
        float ig = sigf(xi.y + g_bh[j2 + 1]);
        float ug = tanh_fast(xu.y + g_bh[161 + j2]);
        float og = sigf(xo.y + g_bh[321 + j2]);
        cv.y = ig * ug;
        hv.y = og * tanh_fast(cv.y);
    }
    *(float2*)(g_C + (size_t)p * 150 + j2) = cv;
    *(float2*)(out + (size_t)p * 150 + j2) = hv;
    g_H2[hpos(p, j2)]     = to_tf32(hv.x);
    g_H2[hpos(p, j2 + 1)] = to_tf32(hv.y);
}

// =================== internal level (GEMM path, d=1..3) ========================
__global__ void level_kernel(float* __restrict__ out, int off_p, int off_c, int n)
{
    int idx = blockIdx.x * blockDim.x + threadIdx.x;
    if (idx >= n * 160) return;
    int p = idx / 160, j = idx - p * 160;
    int g = off_p + p;
    if (j >= 150) { g_H2[hpos(g, j)] = 0.0f; return; }
    const float* Xr = g_X + (size_t)g * 640;
    const float* Pr = g_P + (size_t)p * 480;

    float ig = sigf(Xr[j]        + Pr[j]       + g_bh[j]);
    float ug = tanh_fast(Xr[160 + j] + Pr[160 + j] + g_bh[160 + j]);
    float og = sigf(Xr[320 + j]  + Pr[320 + j] + g_bh[320 + j]);
    float xf = Xr[480 + j] + g_bh[480 + j];

    float fc = 0.0f;
#pragma unroll
    for (int k = 0; k < 4; k++) {
        int cl = 4 * p + k;
        float f = sigf(xf + g_F[(size_t)cl * 160 + j]);
        fc = fmaf(f, g_C[(size_t)(off_c + cl) * 150 + j], fc);
    }
    float c = fmaf(ig, ug, fc);
    g_C[(size_t)g * 150 + j] = c;
    float h = og * tanh_fast(c);
    out[(size_t)g * 150 + j] = h;
    g_H2[hpos(g, j)] = to_tf32(h);
}

// =================== fused small level (d=4..8, n<=256) ========================
__global__ __launch_bounds__(160)
void small_level_kernel(float* __restrict__ out, int off_p, int off_c)
{
    int p = blockIdx.x, j = threadIdx.x;
    __shared__ float hs[160];
    __shared__ float hch[4][160];
    int g = off_p + p;
    float h0 = g_H2[hpos(off_c + 4 * p + 0, j)];
    float h1 = g_H2[hpos(off_c + 4 * p + 1, j)];
    float h2 = g_H2[hpos(off_c + 4 * p + 2, j)];
    float h3 = g_H2[hpos(off_c + 4 * p + 3, j)];
    hch[0][j] = h0; hch[1][j] = h1; hch[2][j] = h2; hch[3][j] = h3;
    hs[j] = h0 + h1 + h2 + h3;
    __syncthreads();

    float di = 0.f, du = 0.f, dog = 0.f;
    float df0 = 0.f, df1 = 0.f, df2 = 0.f, df3 = 0.f;
#pragma unroll 4
    for (int m = 0; m < 160; m++) {
        float hm = hs[m];
        const float* wrow = g_Wh2 + m * 640;
        di  = fmaf(hm, wrow[j], di);
        du  = fmaf(hm, wrow[160 + j], du);
        dog = fmaf(hm, wrow[320 + j], dog);
        float wf = wrow[480 + j];
        df0 = fmaf(hch[0][m], wf, df0);
        df1 = fmaf(hch[1][m], wf, df1);
        df2 = fmaf(hch[2][m], wf, df2);
        df3 = fmaf(hch[3][m], wf, df3);
    }
    if (j < 150) {
        const float* Xr = g_X + (size_t)g * 640;
        float ig = sigf(Xr[j] + di + g_bh[j]);
        float ug = tanh_fast(Xr[160 + j] + du + g_bh[160 + j]);
        float og = sigf(Xr[320 + j] + dog + g_bh[320 + j]);
        float xf = Xr[480 + j] + g_bh[480 + j];
        float fc = sigf(xf + df0) * g_C[(size_t)(off_c + 4 * p + 0) * 150 + j]
                 + sigf(xf + df1) * g_C[(size_t)(off_c + 4 * p + 1) * 150 + j]
                 + sigf(xf + df2) * g_C[(size_t)(off_c + 4 * p + 2) * 150 + j]
                 + sigf(xf + df3) * g_C[(size_t)(off_c + 4 * p + 3) * 150 + j];
        float c = fmaf(ig, ug, fc);
        g_C[(size_t)g * 150 + j] = c;
        float h = og * tanh_fast(c);
        out[(size_t)g * 150 + j] = h;
        g_H2[hpos(g, j)] = to_tf32(h);
    } else {
        g_H2[hpos(g, j)] = 0.0f;
    }
}

// =================== host orchestration ========================================
extern "C" void kernel_launch(void* const* d_in, const int* in_sizes, int n_in,
                              void* d_out, int out_size)
{
    const float* embs = (const float*)d_in[0];
    const float* Wix = (const float*)d_in[1];  const float* bix = (const float*)d_in[2];
    const float* Wfx = (const float*)d_in[3];  const float* bfx = (const float*)d_in[4];
    const float* Wux = (const float*)d_in[5];  const float* bux = (const float*)d_in[6];
    const float* Wox = (const float*)d_in[7];  const float* box_ = (const float*)d_in[8];
    const float* Wih = (const float*)d_in[9];  const float* bih = (const float*)d_in[10];
    const float* Wfh = (const float*)d_in[11]; const float* bfh = (const float*)d_in[12];
    const float* Wuh = (const float*)d_in[13]; const float* buh = (const float*)d_in[14];
    const float* Woh = (const float*)d_in[15]; const float* boh = (const float*)d_in[16];
    float* out = (float*)d_out;

    float *pX, *pH2, *pHS2, *pWxp, *pWhp, *pbx, *pP, *pF;
    cudaGetSymbolAddress((void**)&pX,   g_X);
    cudaGetSymbolAddress((void**)&pH2,  g_H2);
    cudaGetSymbolAddress((void**)&pHS2, g_HS2);
    cudaGetSymbolAddress((void**)&pWxp, g_Wxp);
    cudaGetSymbolAddress((void**)&pWhp, g_Whp);
    cudaGetSymbolAddress((void**)&pbx,  g_bx);
    cudaGetSymbolAddress((void**)&pP,   g_P);
    cudaGetSymbolAddress((void**)&pF,   g_F);

    static const int SIZES[9] = {65536, 16384, 4096, 1024, 256, 64, 16, 4, 1};
    static const int OFF[9]   = {0, 65536, 81920, 86016, 87040, 87296, 87360, 87376, 87380};
    const int SMEM = 3 * 4672 * 4;   // 56064 B

    cudaFuncSetAttribute(gemm_tf32<false, true>,
                         cudaFuncAttributeMaxDynamicSharedMemorySize, SMEM);
    cudaFuncSetAttribute(gemm_tf32<true, false>,
                         cudaFuncAttributeMaxDynamicSharedMemorySize, SMEM);

    // 1. pack weights
    pack_kernel<<<512, 256>>>(Wix, bix, Wfx, bfx, Wux, bux, Wox, box_,
                              Wih, bih, Wfh, bfh, Wuh, buh, Woh, boh);

    // 2. X projections straight from embs (LDG + cvt.rna in-GEMM, no pre-pass)
    //    leaves: gates [i|u|o] only; internal nodes: all 4 gates.
    {
        dim3 grid(3, 512);
        gemm_tf32<false, true><<<grid, 256, SMEM>>>(embs, 300, NLEAF, pWxp, 0,
                                                    pX, 640, pbx, 19, 300);
    }
    {
        dim3 grid(4, 171);
        gemm_tf32<false, true><<<grid, 256, SMEM>>>(embs + (size_t)NLEAF * 300, 300,
                                                    NNODES - NLEAF, pWxp, 0,
                                                    pX + (size_t)NLEAF * 640, 640,
                                                    pbx, 19, 300);
    }

    // 3. leaves
    leaf_kernel<<<(NLEAF * 80 + 255) / 256, 256>>>(out);

    // 4. levels 1..3: GEMM path
    for (int d = 1; d <= 3; d++) {
        int n  = SIZES[d];
        int np = SIZES[d - 1];
        hsum_kernel<<<((n >> 7) * 10 * 1024 + 255) / 256, 256>>>(OFF[d - 1], n);
        {   // P = h_sum @ [W_ih|W_uh|W_oh]
            dim3 grid(3, n / 128);
            gemm_tf32<true, false><<<grid, 256, SMEM>>>(pHS2, 10, n, pWhp, 0,
                                                        pP, 480, nullptr, 10, 160);
        }
        {   // F = h_children @ W_fh  (B cols 480..639)
            dim3 grid(1, np / 128);
            gemm_tf32<true, false><<<grid, 256, SMEM>>>(pH2 + (size_t)OFF[d - 1] * 160,
                                                        10, np, pWhp, 480,
                                                        pF, 160, nullptr, 10, 160);
        }
        level_kernel<<<(n * 160 + 255) / 256, 256>>>(out, OFF[d], OFF[d - 1], n);
    }

    // 5. levels 4..8: fused fp32 kernels (n = 256, 64, 16, 4, 1)
    for (int d = 4; d <= 8; d++)
        small_level_kernel<<<SIZES[d], 160>>>(out, OFF[d], OFF[d - 1]);
}

// round 11
// speedup vs baseline: 1.1136x; 1.1136x over previous
#include <cuda_runtime.h>
#include <cuda_fp16.h>
#include <cstdint>
#include <math.h>

#define NNODES 87381
#define NLEAF  65536

// =================== scratch (device globals; no allocation) =================
// Tiled-interleaved layout for all GEMM A operands (128-row x 16-col chunks):
//   float index(row,k) = (rowblk*NCH + chunk)*2048 + ((s*128+m)*4 + c4)*2 + half
//   chunk=k>>4, kk=k&15, s=kk>>3, c4=kk&3, half=(kk&7)>>2, m=row&127.
__device__ float  g_E2[683u * 19 * 2048];  // tf32-rounded embs, tiled
__device__ __half g_X [88064u * 640];      // x-projections [i|u|o|f], fp16
__device__ float  g_H2[683u * 10 * 2048];  // tf32-rounded h, tiled, 160-padded
__device__ float  g_HS2[128u * 10 * 2048]; // tf32-rounded child-sum, tiled
__device__ float  g_C [NNODES * 150];      // cell states (exact fp32)
__device__ __half g_P [16384u * 480];      // parent projections [i|u|o], fp16
__device__ __half g_F [65536u * 160];      // child f-projections, fp16
// B operands, fragment-row layout: [chunk][s][c4][col(640)][half] (rows of 1280)
__device__ float g_Wxp[19 * 10240];        // Wx packed, tf32-rounded, K pad 304
__device__ float g_Whp[10 * 10240];        // Wh packed, tf32-rounded, K pad 160
__device__ float g_Wh2[160 * 640];         // Wh plain [k][i|u|o|f] for small levels
__device__ float g_bx[640];
__device__ float g_bh[640];

// =================== helpers ==================================================
__device__ __forceinline__ float to_tf32(float x) {
    unsigned u;
    asm("cvt.rna.tf32.f32 %0, %1;" : "=r"(u) : "f"(x));
    return __uint_as_float(u);
}
__device__ __forceinline__ float sigf(float x) {
    return __fdividef(1.0f, 1.0f + __expf(-x));
}
__device__ __forceinline__ float tanh_fast(float x) {
    return __fdividef(2.0f, 1.0f + __expf(-2.0f * x)) - 1.0f;
}
__device__ __forceinline__ size_t hpos(int row, int j) {
    int rb = row >> 7, m = row & 127;
    int chunk = j >> 4, kk = j & 15;
    int s = kk >> 3, r = kk & 7;
    return ((size_t)(rb * 10 + chunk) << 11) + (size_t)((((s << 7) + m) * 4 + (r & 3)) * 2 + (r >> 2));
}
__device__ __forceinline__ void mma8(float* d, const unsigned* a, const unsigned* b) {
    asm volatile(
        "mma.sync.aligned.m16n8k8.row.col.f32.tf32.tf32.f32 "
        "{%0,%1,%2,%3}, {%4,%5,%6,%7}, {%8,%9}, {%0,%1,%2,%3};\n"
        : "+f"(d[0]), "+f"(d[1]), "+f"(d[2]), "+f"(d[3])
        : "r"(a[0]), "r"(a[1]), "r"(a[2]), "r"(a[3]), "r"(b[0]), "r"(b[1]));
}
__device__ __forceinline__ void cp16(uint32_t dst, const void* src) {
    asm volatile("cp.async.ca.shared.global [%0], [%1], 16;" :: "r"(dst), "l"(src));
}
#define CP_COMMIT() asm volatile("cp.async.commit_group;" ::: "memory")
#define CP_WAIT2()  asm volatile("cp.async.wait_group 2;" ::: "memory")

// =================== embs -> tiled tf32 ======================================
__global__ void round_embs_kernel(const float* __restrict__ embs)
{
    int o2 = blockIdx.x * blockDim.x + threadIdx.x;     // float2 index
    const int TOT = 683 * 19 * 1024;
    if (o2 >= TOT) return;
    int w2 = o2 & 1023, t = o2 >> 10;
    int chunk = t % 19, rb = t / 19;
    int c4 = w2 & 3, m = (w2 >> 2) & 127, s = w2 >> 9;
    int row = (rb << 7) + m;
    int k = chunk * 16 + s * 8 + c4;                    // pair (k, k+4)
    float2 v = make_float2(0.f, 0.f);
    if (row < NNODES) {
        const float* er = embs + (size_t)row * 300;
        if (k < 300)     v.x = er[k];
        if (k + 4 < 300) v.y = er[k + 4];
    }
    v.x = to_tf32(v.x);
    v.y = to_tf32(v.y);
    ((float2*)g_E2)[o2] = v;
}

// =================== weight packing ==========================================
__global__ void pack_kernel(
    const float* Wix, const float* bix, const float* Wfx, const float* bfx,
    const float* Wux, const float* bux, const float* Wox, const float* box_,
    const float* Wih, const float* bih, const float* Wfh, const float* bfh,
    const float* Wuh, const float* buh, const float* Woh, const float* boh)
{
    const int T0 = 19 * 10240;          // Wxp
    const int T1 = T0 + 10 * 10240;     // Whp
    const int T2 = T1 + 160 * 640;      // Wh2
    const int T3 = T2 + 640;            // bx
    const int T4 = T3 + 640;            // bh
    for (int idx = blockIdx.x * blockDim.x + threadIdx.x; idx < T4;
         idx += gridDim.x * blockDim.x) {
        if (idx < T0) {
            int rowI = idx / 1280, w = idx % 1280;
            int col = w >> 1, half = w & 1;
            int chunk = rowI >> 3, rr = rowI & 7;
            int k = chunk * 16 + (rr >> 2) * 8 + half * 4 + (rr & 3);
            int m = col / 160, cc = col % 160;
            float v = 0.f;
            if (k < 300 && cc < 150) {
                const float* W = (m == 0) ? Wix : (m == 1) ? Wux : (m == 2) ? Wox : Wfx;
                v = W[k * 150 + cc];
            }
            g_Wxp[idx] = to_tf32(v);
        } else if (idx < T1) {
            int t = idx - T0;
            int rowI = t / 1280, w = t % 1280;
            int col = w >> 1, half = w & 1;
            int chunk = rowI >> 3, rr = rowI & 7;
            int k = chunk * 16 + (rr >> 2) * 8 + half * 4 + (rr & 3);
            int m = col / 160, cc = col % 160;
            float v = 0.f;
            if (k < 150 && cc < 150) {
                const float* W = (m == 0) ? Wih : (m == 1) ? Wuh : (m == 2) ? Woh : Wfh;
                v = W[k * 150 + cc];
            }
            g_Whp[t] = to_tf32(v);
        } else if (idx < T2) {
            int t = idx - T1;
            int k = t / 640, c = t % 640, m = c / 160, cc = c % 160;
            float v = 0.f;
            if (k < 150 && cc < 150) {
                const float* W = (m == 0) ? Wih : (m == 1) ? Wuh : (m == 2) ? Woh : Wfh;
                v = W[k * 150 + cc];
            }
            g_Wh2[t] = v;
        } else if (idx < T3) {
            int c = idx - T2, m = c / 160, cc = c % 160;
            float v = 0.f;
            if (cc < 150) {
                const float* b = (m == 0) ? bix : (m == 1) ? bux : (m == 2) ? box_ : bfx;
                v = b[cc];
            }
            g_bx[c] = v;
        } else {
            int c = idx - T3, m = c / 160, cc = c % 160;
            float v = 0.f;
            if (cc < 150) {
                const float* b = (m == 0) ? bih : (m == 1) ? buh : (m == 2) ? boh : bfh;
                v = b[cc];
            }
            g_bh[c] = v;
        }
    }
}

// =================== tf32 mma GEMM (R5 config, fp16 output) ===================
// BM=128, BN=160, 3-stage cp.async, 256 thr = 8 warps (2m x 4n), warp 64x40.
// C is __half, written as __half2 pairs.
template<bool BIAS>
__global__ __launch_bounds__(256, 2)
void gemm_tf32(const float* __restrict__ A2, int nch,
               const float* __restrict__ Bp, int col0,
               __half* __restrict__ C, int ldc,
               const float* __restrict__ bias, int nchunk)
{
    extern __shared__ __align__(16) float sm[];
    const uint32_t sbase = (uint32_t)__cvta_generic_to_shared(sm);

    const int tid    = threadIdx.x;
    const int lane   = tid & 31;
    const int wid    = tid >> 5;
    const int m_warp = (wid >> 2) * 64;
    const int n_warp = (wid & 3) * 40;
    const int m0     = blockIdx.x * 128;
    const int colblk = blockIdx.y * 160;
    const int bcol0  = col0 + colblk;
    const int c4     = lane & 3;
    const int q      = lane >> 2;

    float acc[4][5][4];
#pragma unroll
    for (int i = 0; i < 4; i++)
#pragma unroll
        for (int j = 0; j < 5; j++)
#pragma unroll
            for (int p = 0; p < 4; p++) acc[i][j][p] = 0.0f;

    auto issue = [&](int st, int ch) {
        if (ch < nchunk) {
            const float* At = A2 + ((size_t)blockIdx.x * nch + ch) * 2048;
            uint32_t da = sbase + st * 18688 + tid * 16;
            cp16(da, At + tid * 4);
            cp16(da + 4096, At + tid * 4 + 1024);
            const float* Bt = Bp + (size_t)ch * 10240 + (size_t)bcol0 * 2;
#pragma unroll
            for (int e = 0; e < 3; e++) {
                int id = tid + e * 256;
                if (id < 640) {
                    int r = id / 80, o = id - r * 80;
                    cp16(sbase + st * 18688 + 8192 + r * 1312 + o * 16,
                         Bt + r * 1280 + o * 4);
                }
            }
        }
        CP_COMMIT();
    };

    issue(0, 0);
    issue(1, 1);
    issue(2, 2);

    int st = 0;
    for (int ch = 0; ch < nchunk; ch++) {
        CP_WAIT2();
        __syncthreads();
        const float* stf = sm + st * 4672;
        const float2* Af = (const float2*)stf;
        const float2* Bf = (const float2*)(stf + 2048);

#pragma unroll
        for (int s = 0; s < 2; s++) {
            unsigned a[4][4];
#pragma unroll
            for (int i = 0; i < 4; i++) {
                int m1 = m_warp + 16 * i + q;
                float2 lo = Af[(s * 128 + m1) * 4 + c4];
                float2 hi = Af[(s * 128 + m1 + 8) * 4 + c4];
                a[i][0] = __float_as_uint(lo.x);
                a[i][1] = __float_as_uint(hi.x);
                a[i][2] = __float_as_uint(lo.y);
                a[i][3] = __float_as_uint(hi.y);
            }
            unsigned b[5][2];
#pragma unroll
            for (int j = 0; j < 5; j++) {
                float2 bv = Bf[(s * 4 + c4) * 164 + n_warp + q + 8 * j];
                b[j][0] = __float_as_uint(bv.x);
                b[j][1] = __float_as_uint(bv.y);
            }
#pragma unroll
            for (int i = 0; i < 4; i++)
#pragma unroll
                for (int j = 0; j < 5; j++) mma8(acc[i][j], a[i], b[j]);
        }
        __syncthreads();
        issue(st, ch + 3);
        st = (st == 2) ? 0 : st + 1;
    }

    const int r0 = m0 + m_warp + q;
    const int cl = n_warp + c4 * 2;
#pragma unroll
    for (int i = 0; i < 4; i++) {
#pragma unroll
        for (int h = 0; h < 2; h++) {
            int r = r0 + 16 * i + 8 * h;
            __half* crow = C + (size_t)r * ldc + colblk;
#pragma unroll
            for (int j = 0; j < 5; j++) {
                int c = cl + 8 * j;
                float v0 = acc[i][j][2 * h], v1 = acc[i][j][2 * h + 1];
                if (BIAS) {
                    v0 += bias[bcol0 + c];
                    v1 += bias[bcol0 + c + 1];
                }
                *(__half2*)(crow + c) = __floats2half2_rn(v0, v1);
            }
        }
    }
}

// =================== child-sum of h (tiled -> tiled, tf32) ====================
__global__ void hsum_kernel(int off_c, int n)
{
    int o2 = blockIdx.x * blockDim.x + threadIdx.x;     // float2 index into HS2
    const int TOT = (n >> 7) * 10 * 1024;
    if (o2 >= TOT) return;
    int w2 = o2 & 1023, t = o2 >> 10;
    int chunk = t % 10, rb = t / 10;
    int c4 = w2 & 3, m = (w2 >> 2) & 127, s = w2 >> 9;
    int p = (rb << 7) + m;
    const float2* H2 = (const float2*)g_H2;
    float2 a = make_float2(0.f, 0.f);
#pragma unroll
    for (int k = 0; k < 4; k++) {
        int crow = off_c + 4 * p + k;
        float2 hv = H2[((size_t)((crow >> 7) * 10 + chunk) << 10) +
                       (size_t)(((s << 7) + (crow & 127)) * 4 + c4)];
        a.x += hv.x;
        a.y += hv.y;
    }
    a.x = to_tf32(a.x);
    a.y = to_tf32(a.y);
    ((float2*)g_HS2)[o2] = a;
}

// =================== leaves (float2-vectorized, half X) ========================
__global__ void leaf_kernel(float* __restrict__ out)
{
    int idx = blockIdx.x * blockDim.x + threadIdx.x;
    if (idx >= NLEAF * 80) return;
    int p = idx / 80, j2 = (idx - p * 80) * 2;
    if (j2 >= 150) {
        g_H2[hpos(p, j2)] = 0.0f;
        g_H2[hpos(p, j2 + 1)] = 0.0f;
        return;
    }
    const __half* Xr = g_X + (size_t)p * 640;
    float2 xi = __half22float2(*(const __half2*)(Xr + j2));
    float2 xu = __half22float2(*(const __half2*)(Xr + 160 + j2));
    float2 xo = __half22float2(*(const __half2*)(Xr + 320 + j2));
    float2 cv, hv;
    {
        float ig = sigf(xi.x + g_bh[j2]);
        float ug = tanh_fast(xu.x + g_bh[160 + j2]);
        float og = sigf(xo.x + g_bh[320 + j2]);
        cv.x = ig * ug;
        hv.x = og * tanh_fast(cv.x);
    }
    {
        float ig = sigf(xi.y + g_bh[j2 + 1]);
        float ug = tanh_fast(xu.y + g_bh[161 + j2]);
        float og = sigf(xo.y + g_bh[321 + j2]);
        cv.y = ig * ug;
        hv.y = og * tanh_fast(cv.y);
    }
    *(float2*)(g_C + (size_t)p * 150 + j2) = cv;
    *(float2*)(out + (size_t)p * 150 + j2) = hv;
    g_H2[hpos(p, j2)]     = to_tf32(hv.x);
    g_H2[hpos(p, j2 + 1)] = to_tf32(hv.y);
}

// =================== internal level (GEMM path, d=1..3) ========================
__global__ void level_kernel(float* __restrict__ out, int off_p, int off_c, int n)
{
    int idx = blockIdx.x * blockDim.x + threadIdx.x;
    if (idx >= n * 160) return;
    int p = idx / 160, j = idx - p * 160;
    int g = off_p + p;
    if (j >= 150) { g_H2[hpos(g, j)] = 0.0f; return; }
    const __half* Xr = g_X + (size_t)g * 640;
    const __half* Pr = g_P + (size_t)p * 480;

    float ig = sigf(__half2float(Xr[j])       + __half2float(Pr[j])       + g_bh[j]);
    float ug = tanh_fast(__half2float(Xr[160 + j]) + __half2float(Pr[160 + j]) + g_bh[160 + j]);
    float og = sigf(__half2float(Xr[320 + j]) + __half2float(Pr[320 + j]) + g_bh[320 + j]);
    float xf = __half2float(Xr[480 + j]) + g_bh[480 + j];

    float fc = 0.0f;
#pragma unroll
    for (int k = 0; k < 4; k++) {
        int cl = 4 * p + k;
        float f = sigf(xf + __half2float(g_F[(size_t)cl * 160 + j]));
        fc = fmaf(f, g_C[(size_t)(off_c + cl) * 150 + j], fc);
    }
    float c = fmaf(ig, ug, fc);
    g_C[(size_t)g * 150 + j] = c;
    float h = og * tanh_fast(c);
    out[(size_t)g * 150 + j] = h;
    g_H2[hpos(g, j)] = to_tf32(h);
}

// =================== fused small level (d=4..8, n<=256) ========================
__global__ __launch_bounds__(160)
void small_level_kernel(float* __restrict__ out, int off_p, int off_c)
{
    int p = blockIdx.x, j = threadIdx.x;
    __shared__ float hs[160];
    __shared__ float hch[4][160];
    int g = off_p + p;
    float h0 = g_H2[hpos(off_c + 4 * p + 0, j)];
    float h1 = g_H2[hpos(off_c + 4 * p + 1, j)];
    float h2 = g_H2[hpos(off_c + 4 * p + 2, j)];
    float h3 = g_H2[hpos(off_c + 4 * p + 3, j)];
    hch[0][j] = h0; hch[1][j] = h1; hch[2][j] = h2; hch[3][j] = h3;
    hs[j] = h0 + h1 + h2 + h3;
    __syncthreads();

    float di = 0.f, du = 0.f, dog = 0.f;
    float df0 = 0.f, df1 = 0.f, df2 = 0.f, df3 = 0.f;
#pragma unroll 4
    for (int m = 0; m < 160; m++) {
        float hm = hs[m];
        const float* wrow = g_Wh2 + m * 640;
        di  = fmaf(hm, wrow[j], di);
        du  = fmaf(hm, wrow[160 + j], du);
        dog = fmaf(hm, wrow[320 + j], dog);
        float wf = wrow[480 + j];
        df0 = fmaf(hch[0][m], wf, df0);
        df1 = fmaf(hch[1][m], wf, df1);
        df2 = fmaf(hch[2][m], wf, df2);
        df3 = fmaf(hch[3][m], wf, df3);
    }
    if (j < 150) {
        const __half* Xr = g_X + (size_t)g * 640;
        float ig = sigf(__half2float(Xr[j]) + di + g_bh[j]);
        float ug = tanh_fast(__half2float(Xr[160 + j]) + du + g_bh[160 + j]);
        float og = sigf(__half2float(Xr[320 + j]) + dog + g_bh[320 + j]);
        float xf = __half2float(Xr[480 + j]) + g_bh[480 + j];
        float fc = sigf(xf + df0) * g_C[(size_t)(off_c + 4 * p + 0) * 150 + j]
                 + sigf(xf + df1) * g_C[(size_t)(off_c + 4 * p + 1) * 150 + j]
                 + sigf(xf + df2) * g_C[(size_t)(off_c + 4 * p + 2) * 150 + j]
                 + sigf(xf + df3) * g_C[(size_t)(off_c + 4 * p + 3) * 150 + j];
        float c = fmaf(ig, ug, fc);
        g_C[(size_t)g * 150 + j] = c;
        float h = og * tanh_fast(c);
        out[(size_t)g * 150 + j] = h;
        g_H2[hpos(g, j)] = to_tf32(h);
    } else {
        g_H2[hpos(g, j)] = 0.0f;
    }
}

// =================== host orchestration ========================================
extern "C" void kernel_launch(void* const* d_in, const int* in_sizes, int n_in,
                              void* d_out, int out_size)
{
    const float* embs = (const float*)d_in[0];
    const float* Wix = (const float*)d_in[1];  const float* bix = (const float*)d_in[2];
    const float* Wfx = (const float*)d_in[3];  const float* bfx = (const float*)d_in[4];
    const float* Wux = (const float*)d_in[5];  const float* bux = (const float*)d_in[6];
    const float* Wox = (const float*)d_in[7];  const float* box_ = (const float*)d_in[8];
    const float* Wih = (const float*)d_in[9];  const float* bih = (const float*)d_in[10];
    const float* Wfh = (const float*)d_in[11]; const float* bfh = (const float*)d_in[12];
    const float* Wuh = (const float*)d_in[13]; const float* buh = (const float*)d_in[14];
    const float* Woh = (const float*)d_in[15]; const float* boh = (const float*)d_in[16];
    float* out = (float*)d_out;

    float *pE2, *pH2, *pHS2, *pWxp, *pWhp, *pbx;
    __half *pX, *pP, *pF;
    cudaGetSymbolAddress((void**)&pE2,  g_E2);
    cudaGetSymbolAddress((void**)&pX,   g_X);
    cudaGetSymbolAddress((void**)&pH2,  g_H2);
    cudaGetSymbolAddress((void**)&pHS2, g_HS2);
    cudaGetSymbolAddress((void**)&pWxp, g_Wxp);
    cudaGetSymbolAddress((void**)&pWhp, g_Whp);
    cudaGetSymbolAddress((void**)&pbx,  g_bx);
    cudaGetSymbolAddress((void**)&pP,   g_P);
    cudaGetSymbolAddress((void**)&pF,   g_F);

    static const int SIZES[9] = {65536, 16384, 4096, 1024, 256, 64, 16, 4, 1};
    static const int OFF[9]   = {0, 65536, 81920, 86016, 87040, 87296, 87360, 87376, 87380};
    const int SMEM = 3 * 4672 * 4;   // 56064 B

    cudaFuncSetAttribute(gemm_tf32<true>,
                         cudaFuncAttributeMaxDynamicSharedMemorySize, SMEM);
    cudaFuncSetAttribute(gemm_tf32<false>,
                         cudaFuncAttributeMaxDynamicSharedMemorySize, SMEM);

    // 1. pre-round + tile embs; pack weights
    round_embs_kernel<<<(683 * 19 * 1024 + 255) / 256, 256>>>(embs);
    pack_kernel<<<512, 256>>>(Wix, bix, Wfx, bfx, Wux, bux, Wox, box_,
                              Wih, bih, Wfh, bfh, Wuh, buh, Woh, boh);

    // 2. X projections: leaves need [i|u|o] only; internal nodes all 4 gates
    {
        dim3 grid(512, 3);
        gemm_tf32<true><<<grid, 256, SMEM>>>(pE2, 19, pWxp, 0, pX, 640, pbx, 19);
    }
    {
        dim3 grid(171, 4);
        gemm_tf32<true><<<grid, 256, SMEM>>>(pE2 + (size_t)512 * 19 * 2048, 19, pWxp, 0,
                                             pX + (size_t)65536 * 640, 640, pbx, 19);
    }

    // 3. leaves
    leaf_kernel<<<(NLEAF * 80 + 255) / 256, 256>>>(out);

    // 4. levels 1..3: GEMM path
    for (int d = 1; d <= 3; d++) {
        int n  = SIZES[d];
        int np = SIZES[d - 1];
        hsum_kernel<<<((n >> 7) * 10 * 1024 + 255) / 256, 256>>>(OFF[d - 1], n);
        {   // P = h_sum @ [W_ih|W_uh|W_oh]
            dim3 grid(n / 128, 3);
            gemm_tf32<false><<<grid, 256, SMEM>>>(pHS2, 10, pWhp, 0, pP, 480, nullptr, 10);
        }
        {   // F = h_children @ W_fh  (B cols 480..639)
            dim3 grid(np / 128, 1);
            gemm_tf32<false><<<grid, 256, SMEM>>>(pH2 + (size_t)OFF[d - 1] * 160, 10,
                                                  pWhp, 480, pF, 160, nullptr, 10);
        }
        level_kernel<<<(n * 160 + 255) / 256, 256>>>(out, OFF[d], OFF[d - 1], n);
    }

    // 5. levels 4..8: fused fp32 kernels (n = 256, 64, 16, 4, 1)
    for (int d = 4; d <= 8; d++)
        small_level_kernel<<<SIZES[d], 160>>>(out, OFF[d], OFF[d - 1]);
}

// round 12
// speedup vs baseline: 1.3830x; 1.2420x over previous
#include <cuda_runtime.h>
#include <cuda_fp16.h>
#include <cstdint>
#include <math.h>

#define NNODES 87381
#define NLEAF  65536

// =================== scratch (device globals; no allocation) =================
// Tiled half2 layout for GEMM A operands (128-row x 16-col chunks):
//   half2 word(row,k2) = base[(rowblk*NCH + chunk)*1024 + (s*128+m)*4 + c4]
//   where chunk=k>>4, kk=k&15, s=kk>>3, c4=(kk&7)>>1; word = (k_even, k_odd).
// Matches mma.m16n8k16 A fragment: regs = {row q,q+8} x {k-offset 0,8}.
__device__ __align__(16) __half g_E2[683u * 19 * 2048];  // fp16 embs, tiled
__device__ __align__(16) __half g_X [88064u * 640];      // x-projections [i|u|o|f]
__device__ __align__(16) __half g_H2[683u * 10 * 2048];  // fp16 h, tiled, 160-pad
__device__ __align__(16) __half g_HS2[128u * 10 * 2048]; // fp16 child-sum, tiled
__device__ float  g_C [NNODES * 150];                    // cell states (fp32)
__device__ __align__(16) __half g_P [16384u * 480];      // parent proj [i|u|o]
__device__ __align__(16) __half g_F [65536u * 160];      // child f-projections
// B operands: [chunk][s][c4][col(640)][parity] halves (rows of 1280 halves)
__device__ __align__(16) __half g_Wxp[19 * 10240];       // Wx packed fp16, K pad 304
__device__ __align__(16) __half g_Whp[10 * 10240];       // Wh packed fp16, K pad 160
__device__ float g_Wh2[160 * 640];        // Wh plain fp32 for small levels
__device__ float g_bx[640];
__device__ float g_bh[640];

// =================== helpers ==================================================
__device__ __forceinline__ float sigf(float x) {
    return __fdividef(1.0f, 1.0f + __expf(-x));
}
__device__ __forceinline__ float tanh_fast(float x) {
    return __fdividef(2.0f, 1.0f + __expf(-2.0f * x)) - 1.0f;
}
// half-element index of h(row, j) in tiled H buffer (NCH = 10)
__device__ __forceinline__ size_t hpos(int row, int j) {
    int rb = row >> 7, m = row & 127;
    int chunk = j >> 4, kk = j & 15;
    int s = kk >> 3, r = kk & 7;
    return ((size_t)(rb * 10 + chunk) << 11) +
           (size_t)((((s << 7) + m) * 4 + (r >> 1)) * 2 + (r & 1));
}
__device__ __forceinline__ void mma16(float* d, const unsigned* a, const unsigned* b) {
    asm volatile(
        "mma.sync.aligned.m16n8k16.row.col.f32.f16.f16.f32 "
        "{%0,%1,%2,%3}, {%4,%5,%6,%7}, {%8,%9}, {%0,%1,%2,%3};\n"
        : "+f"(d[0]), "+f"(d[1]), "+f"(d[2]), "+f"(d[3])
        : "r"(a[0]), "r"(a[1]), "r"(a[2]), "r"(a[3]), "r"(b[0]), "r"(b[1]));
}
__device__ __forceinline__ void cp16(uint32_t dst, const void* src) {
    asm volatile("cp.async.ca.shared.global [%0], [%1], 16;" :: "r"(dst), "l"(src));
}
#define CP_COMMIT() asm volatile("cp.async.commit_group;" ::: "memory")
#define CP_WAIT2()  asm volatile("cp.async.wait_group 2;" ::: "memory")

// =================== embs -> tiled fp16 ======================================
__global__ void round_embs_kernel(const float* __restrict__ embs)
{
    int o2 = blockIdx.x * blockDim.x + threadIdx.x;     // half2 word index
    const int TOT = 683 * 19 * 1024;
    if (o2 >= TOT) return;
    int w2 = o2 & 1023, t = o2 >> 10;
    int chunk = t % 19, rb = t / 19;
    int c4 = w2 & 3, m = (w2 >> 2) & 127, s = w2 >> 9;
    int row = (rb << 7) + m;
    int k = chunk * 16 + s * 8 + c4 * 2;                // pair (k, k+1)
    float vx = 0.f, vy = 0.f;
    if (row < NNODES) {
        const float* er = embs + (size_t)row * 300;
        if (k < 300)     vx = er[k];
        if (k + 1 < 300) vy = er[k + 1];
    }
    ((__half2*)g_E2)[o2] = __floats2half2_rn(vx, vy);
}

// =================== weight packing ==========================================
__global__ void pack_kernel(
    const float* Wix, const float* bix, const float* Wfx, const float* bfx,
    const float* Wux, const float* bux, const float* Wox, const float* box_,
    const float* Wih, const float* bih, const float* Wfh, const float* bfh,
    const float* Wuh, const float* buh, const float* Woh, const float* boh)
{
    const int T0 = 19 * 10240;          // Wxp (halves)
    const int T1 = T0 + 10 * 10240;     // Whp (halves)
    const int T2 = T1 + 160 * 640;      // Wh2 (floats)
    const int T3 = T2 + 640;            // bx
    const int T4 = T3 + 640;            // bh
    for (int idx = blockIdx.x * blockDim.x + threadIdx.x; idx < T4;
         idx += gridDim.x * blockDim.x) {
        if (idx < T0) {
            int rowI = idx / 1280, w = idx % 1280;
            int col = w >> 1, par = w & 1;
            int chunk = rowI >> 3, rr = rowI & 7;
            int k = chunk * 16 + (rr >> 2) * 8 + (rr & 3) * 2 + par;
            int m = col / 160, cc = col % 160;
            float v = 0.f;
            if (k < 300 && cc < 150) {
                const float* W = (m == 0) ? Wix : (m == 1) ? Wux : (m == 2) ? Wox : Wfx;
                v = W[k * 150 + cc];
            }
            g_Wxp[idx] = __float2half_rn(v);
        } else if (idx < T1) {
            int t = idx - T0;
            int rowI = t / 1280, w = t % 1280;
            int col = w >> 1, par = w & 1;
            int chunk = rowI >> 3, rr = rowI & 7;
            int k = chunk * 16 + (rr >> 2) * 8 + (rr & 3) * 2 + par;
            int m = col / 160, cc = col % 160;
            float v = 0.f;
            if (k < 150 && cc < 150) {
                const float* W = (m == 0) ? Wih : (m == 1) ? Wuh : (m == 2) ? Woh : Wfh;
                v = W[k * 150 + cc];
            }
            g_Whp[t] = __float2half_rn(v);
        } else if (idx < T2) {
            int t = idx - T1;
            int k = t / 640, c = t % 640, m = c / 160, cc = c % 160;
            float v = 0.f;
            if (k < 150 && cc < 150) {
                const float* W = (m == 0) ? Wih : (m == 1) ? Wuh : (m == 2) ? Woh : Wfh;
                v = W[k * 150 + cc];
            }
            g_Wh2[t] = v;
        } else if (idx < T3) {
            int c = idx - T2, m = c / 160, cc = c % 160;
            float v = 0.f;
            if (cc < 150) {
                const float* b = (m == 0) ? bix : (m == 1) ? bux : (m == 2) ? box_ : bfx;
                v = b[cc];
            }
            g_bx[c] = v;
        } else {
            int c = idx - T3, m = c / 160, cc = c % 160;
            float v = 0.f;
            if (cc < 150) {
                const float* b = (m == 0) ? bih : (m == 1) ? buh : (m == 2) ? boh : bfh;
                v = b[cc];
            }
            g_bh[c] = v;
        }
    }
}

// =================== fp16 mma GEMM (m16n8k16), 3-stage cp.async ===============
// BM=128, BN=160, 256 thr = 8 warps (2m x 4n), warp tile 64x40.
// Stage = 9472 B: A 4096 (2048 halves) + B 8 rows x 168 half2 (672 B pitch).
// One k16 MMA step per chunk. All LDS.32 conflict-free.
template<bool BIAS>
__global__ __launch_bounds__(256, 2)
void gemm_fp16(const __half* __restrict__ A2, int nch,
               const __half* __restrict__ Bp, int col0,
               __half* __restrict__ C, int ldc,
               const float* __restrict__ bias, int nchunk)
{
    extern __shared__ __align__(16) char smb[];
    const uint32_t sbase = (uint32_t)__cvta_generic_to_shared(smb);
    const int STGB = 9472;

    const int tid    = threadIdx.x;
    const int lane   = tid & 31;
    const int wid    = tid >> 5;
    const int m_warp = (wid >> 2) * 64;
    const int n_warp = (wid & 3) * 40;
    const int m0     = blockIdx.x * 128;
    const int colblk = blockIdx.y * 160;
    const int bcol0  = col0 + colblk;
    const int c4     = lane & 3;
    const int q      = lane >> 2;

    float acc[4][5][4];
#pragma unroll
    for (int i = 0; i < 4; i++)
#pragma unroll
        for (int j = 0; j < 5; j++)
#pragma unroll
            for (int p = 0; p < 4; p++) acc[i][j][p] = 0.0f;

    auto issue = [&](int st, int ch) {
        if (ch < nchunk) {
            const uint32_t dbase = sbase + st * STGB;
            const __half* At = A2 + ((size_t)blockIdx.x * nch + ch) * 2048;
            cp16(dbase + tid * 16, At + tid * 8);
            const __half* Bt = Bp + (size_t)ch * 10240 + (size_t)bcol0 * 2;
#pragma unroll
            for (int e = 0; e < 2; e++) {
                int id = tid + e * 256;
                if (id < 320) {
                    int r = id / 40, o = id - r * 40;
                    cp16(dbase + 4096 + r * 672 + o * 16, Bt + r * 1280 + o * 8);
                }
            }
        }
        CP_COMMIT();
    };

    issue(0, 0);
    issue(1, 1);
    issue(2, 2);

    int st = 0;
    for (int ch = 0; ch < nchunk; ch++) {
        CP_WAIT2();
        __syncthreads();
        const uint32_t* Au = (const uint32_t*)(smb + (size_t)st * STGB);
        const uint32_t* Bu = (const uint32_t*)(smb + (size_t)st * STGB + 4096);

        unsigned b[5][2];
#pragma unroll
        for (int j = 0; j < 5; j++) {
            int col = n_warp + q + 8 * j;
            b[j][0] = Bu[c4 * 168 + col];
            b[j][1] = Bu[(4 + c4) * 168 + col];
        }
#pragma unroll
        for (int i = 0; i < 4; i++) {
            int m1 = m_warp + 16 * i + q;
            unsigned a[4];
            a[0] = Au[m1 * 4 + c4];
            a[1] = Au[(m1 + 8) * 4 + c4];
            a[2] = Au[(128 + m1) * 4 + c4];
            a[3] = Au[(128 + m1 + 8) * 4 + c4];
#pragma unroll
            for (int j = 0; j < 5; j++) mma16(acc[i][j], a, b[j]);
        }
        __syncthreads();
        issue(st, ch + 3);
        st = (st == 2) ? 0 : st + 1;
    }

    const int r0 = m0 + m_warp + q;
    const int cl = n_warp + c4 * 2;
#pragma unroll
    for (int i = 0; i < 4; i++) {
#pragma unroll
        for (int h = 0; h < 2; h++) {
            int r = r0 + 16 * i + 8 * h;
            __half* crow = C + (size_t)r * ldc + colblk;
#pragma unroll
            for (int j = 0; j < 5; j++) {
                int c = cl + 8 * j;
                float v0 = acc[i][j][2 * h], v1 = acc[i][j][2 * h + 1];
                if (BIAS) {
                    v0 += bias[bcol0 + c];
                    v1 += bias[bcol0 + c + 1];
                }
                *(__half2*)(crow + c) = __floats2half2_rn(v0, v1);
            }
        }
    }
}

// =================== child-sum of h (tiled -> tiled, fp16) ====================
__global__ void hsum_kernel(int off_c, int n)
{
    int o2 = blockIdx.x * blockDim.x + threadIdx.x;     // half2 word into HS2
    const int TOT = (n >> 7) * 10 * 1024;
    if (o2 >= TOT) return;
    int w2 = o2 & 1023, t = o2 >> 10;
    int chunk = t % 10, rb = t / 10;
    int p = (rb << 7) + ((w2 >> 2) & 127);
    int sc = (w2 & 3) + ((w2 >> 9) << 9);               // s*512 + m*4 + c4 parts
    const __half2* H2 = (const __half2*)g_H2;
    float ax = 0.f, ay = 0.f;
#pragma unroll
    for (int k = 0; k < 4; k++) {
        int crow = off_c + 4 * p + k;
        float2 hv = __half22float2(
            H2[((size_t)((crow >> 7) * 10 + chunk) << 10) +
               (size_t)(((w2 >> 9) << 9) + ((crow & 127) << 2) + (w2 & 3))]);
        ax += hv.x;
        ay += hv.y;
    }
    (void)sc;
    ((__half2*)g_HS2)[o2] = __floats2half2_rn(ax, ay);
}

// =================== leaves (float2-vectorized, half X) ========================
__global__ void leaf_kernel(float* __restrict__ out)
{
    int idx = blockIdx.x * blockDim.x + threadIdx.x;
    if (idx >= NLEAF * 80) return;
    int p = idx / 80, j2 = (idx - p * 80) * 2;
    if (j2 >= 150) {
        *(__half2*)(g_H2 + hpos(p, j2)) = __floats2half2_rn(0.f, 0.f);
        return;
    }
    const __half* Xr = g_X + (size_t)p * 640;
    float2 xi = __half22float2(*(const __half2*)(Xr + j2));
    float2 xu = __half22float2(*(const __half2*)(Xr + 160 + j2));
    float2 xo = __half22float2(*(const __half2*)(Xr + 320 + j2));
    float2 cv, hv;
    {
        float ig = sigf(xi.x + g_bh[j2]);
        float ug = tanh_fast(xu.x + g_bh[160 + j2]);
        float og = sigf(xo.x + g_bh[320 + j2]);
        cv.x = ig * ug;
        hv.x = og * tanh_fast(cv.x);
    }
    {
        float ig = sigf(xi.y + g_bh[j2 + 1]);
        float ug = tanh_fast(xu.y + g_bh[161 + j2]);
        float og = sigf(xo.y + g_bh[321 + j2]);
        cv.y = ig * ug;
        hv.y = og * tanh_fast(cv.y);
    }
    *(float2*)(g_C + (size_t)p * 150 + j2) = cv;
    *(float2*)(out + (size_t)p * 150 + j2) = hv;
    *(__half2*)(g_H2 + hpos(p, j2)) = __floats2half2_rn(hv.x, hv.y);
}

// =================== internal level (GEMM path, d=1..3) ========================
__global__ void level_kernel(float* __restrict__ out, int off_p, int off_c, int n)
{
    int idx = blockIdx.x * blockDim.x + threadIdx.x;
    if (idx >= n * 160) return;
    int p = idx / 160, j = idx - p * 160;
    int g = off_p + p;
    if (j >= 150) { g_H2[hpos(g, j)] = __float2half_rn(0.f); return; }
    const __half* Xr = g_X + (size_t)g * 640;
    const __half* Pr = g_P + (size_t)p * 480;

    float ig = sigf(__half2float(Xr[j])       + __half2float(Pr[j])       + g_bh[j]);
    float ug = tanh_fast(__half2float(Xr[160 + j]) + __half2float(Pr[160 + j]) + g_bh[160 + j]);
    float og = sigf(__half2float(Xr[320 + j]) + __half2float(Pr[320 + j]) + g_bh[320 + j]);
    float xf = __half2float(Xr[480 + j]) + g_bh[480 + j];

    float fc = 0.0f;
#pragma unroll
    for (int k = 0; k < 4; k++) {
        int cl = 4 * p + k;
        float f = sigf(xf + __half2float(g_F[(size_t)cl * 160 + j]));
        fc = fmaf(f, g_C[(size_t)(off_c + cl) * 150 + j], fc);
    }
    float c = fmaf(ig, ug, fc);
    g_C[(size_t)g * 150 + j] = c;
    float h = og * tanh_fast(c);
    out[(size_t)g * 150 + j] = h;
    g_H2[hpos(g, j)] = __float2half_rn(h);
}

// =================== fused small level (d=4..8, n<=256) ========================
__global__ __launch_bounds__(160)
void small_level_kernel(float* __restrict__ out, int off_p, int off_c)
{
    int p = blockIdx.x, j = threadIdx.x;
    __shared__ float hs[160];
    __shared__ float hch[4][160];
    int g = off_p + p;
    float h0 = __half2float(g_H2[hpos(off_c + 4 * p + 0, j)]);
    float h1 = __half2float(g_H2[hpos(off_c + 4 * p + 1, j)]);
    float h2 = __half2float(g_H2[hpos(off_c + 4 * p + 2, j)]);
    float h3 = __half2float(g_H2[hpos(off_c + 4 * p + 3, j)]);
    hch[0][j] = h0; hch[1][j] = h1; hch[2][j] = h2; hch[3][j] = h3;
    hs[j] = h0 + h1 + h2 + h3;
    __syncthreads();

    float di = 0.f, du = 0.f, dog = 0.f;
    float df0 = 0.f, df1 = 0.f, df2 = 0.f, df3 = 0.f;
#pragma unroll 4
    for (int m = 0; m < 160; m++) {
        float hm = hs[m];
        const float* wrow = g_Wh2 + m * 640;
        di  = fmaf(hm, wrow[j], di);
        du  = fmaf(hm, wrow[160 + j], du);
        dog = fmaf(hm, wrow[320 + j], dog);
        float wf = wrow[480 + j];
        df0 = fmaf(hch[0][m], wf, df0);
        df1 = fmaf(hch[1][m], wf, df1);
        df2 = fmaf(hch[2][m], wf, df2);
        df3 = fmaf(hch[3][m], wf, df3);
    }
    if (j < 150) {
        const __half* Xr = g_X + (size_t)g * 640;
        float ig = sigf(__half2float(Xr[j]) + di + g_bh[j]);
        float ug = tanh_fast(__half2float(Xr[160 + j]) + du + g_bh[160 + j]);
        float og = sigf(__half2float(Xr[320 + j]) + dog + g_bh[320 + j]);
        float xf = __half2float(Xr[480 + j]) + g_bh[480 + j];
        float fc = sigf(xf + df0) * g_C[(size_t)(off_c + 4 * p + 0) * 150 + j]
                 + sigf(xf + df1) * g_C[(size_t)(off_c + 4 * p + 1) * 150 + j]
                 + sigf(xf + df2) * g_C[(size_t)(off_c + 4 * p + 2) * 150 + j]
                 + sigf(xf + df3) * g_C[(size_t)(off_c + 4 * p + 3) * 150 + j];
        float c = fmaf(ig, ug, fc);
        g_C[(size_t)g * 150 + j] = c;
        float h = og * tanh_fast(c);
        out[(size_t)g * 150 + j] = h;
        g_H2[hpos(g, j)] = __float2half_rn(h);
    } else {
        g_H2[hpos(g, j)] = __float2half_rn(0.f);
    }
}

// =================== host orchestration ========================================
extern "C" void kernel_launch(void* const* d_in, const int* in_sizes, int n_in,
                              void* d_out, int out_size)
{
    const float* embs = (const float*)d_in[0];
    const float* Wix = (const float*)d_in[1];  const float* bix = (const float*)d_in[2];
    const float* Wfx = (const float*)d_in[3];  const float* bfx = (const float*)d_in[4];
    const float* Wux = (const float*)d_in[5];  const float* bux = (const float*)d_in[6];
    const float* Wox = (const float*)d_in[7];  const float* box_ = (const float*)d_in[8];
    const float* Wih = (const float*)d_in[9];  const float* bih = (const float*)d_in[10];
    const float* Wfh = (const float*)d_in[11]; const float* bfh = (const float*)d_in[12];
    const float* Wuh = (const float*)d_in[13]; const float* buh = (const float*)d_in[14];
    const float* Woh = (const float*)d_in[15]; const float* boh = (const float*)d_in[16];
    float* out = (float*)d_out;

    __half *pE2, *pX, *pH2, *pHS2, *pWxp, *pWhp, *pP, *pF;
    float *pbx;
    cudaGetSymbolAddress((void**)&pE2,  g_E2);
    cudaGetSymbolAddress((void**)&pX,   g_X);
    cudaGetSymbolAddress((void**)&pH2,  g_H2);
    cudaGetSymbolAddress((void**)&pHS2, g_HS2);
    cudaGetSymbolAddress((void**)&pWxp, g_Wxp);
    cudaGetSymbolAddress((void**)&pWhp, g_Whp);
    cudaGetSymbolAddress((void**)&pbx,  g_bx);
    cudaGetSymbolAddress((void**)&pP,   g_P);
    cudaGetSymbolAddress((void**)&pF,   g_F);

    static const int SIZES[9] = {65536, 16384, 4096, 1024, 256, 64, 16, 4, 1};
    static const int OFF[9]   = {0, 65536, 81920, 86016, 87040, 87296, 87360, 87376, 87380};
    const int SMEM = 3 * 9472;   // 28416 B

    cudaFuncSetAttribute(gemm_fp16<true>,
                         cudaFuncAttributeMaxDynamicSharedMemorySize, SMEM);
    cudaFuncSetAttribute(gemm_fp16<false>,
                         cudaFuncAttributeMaxDynamicSharedMemorySize, SMEM);

    // 1. round + tile embs to fp16; pack weights
    round_embs_kernel<<<(683 * 19 * 1024 + 255) / 256, 256>>>(embs);
    pack_kernel<<<512, 256>>>(Wix, bix, Wfx, bfx, Wux, bux, Wox, box_,
                              Wih, bih, Wfh, bfh, Wuh, buh, Woh, boh);

    // 2. X projections: leaves need [i|u|o] only; internal nodes all 4 gates
    {
        dim3 grid(512, 3);
        gemm_fp16<true><<<grid, 256, SMEM>>>(pE2, 19, pWxp, 0, pX, 640, pbx, 19);
    }
    {
        dim3 grid(171, 4);
        gemm_fp16<true><<<grid, 256, SMEM>>>(pE2 + (size_t)512 * 19 * 2048, 19, pWxp, 0,
                                             pX + (size_t)65536 * 640, 640, pbx, 19);
    }

    // 3. leaves
    leaf_kernel<<<(NLEAF * 80 + 255) / 256, 256>>>(out);

    // 4. levels 1..3: GEMM path
    for (int d = 1; d <= 3; d++) {
        int n  = SIZES[d];
        int np = SIZES[d - 1];
        hsum_kernel<<<((n >> 7) * 10 * 1024 + 255) / 256, 256>>>(OFF[d - 1], n);
        {   // P = h_sum @ [W_ih|W_uh|W_oh]
            dim3 grid(n / 128, 3);
            gemm_fp16<false><<<grid, 256, SMEM>>>(pHS2, 10, pWhp, 0, pP, 480, nullptr, 10);
        }
        {   // F = h_children @ W_fh  (B cols 480..639)
            dim3 grid(np / 128, 1);
            gemm_fp16<false><<<grid, 256, SMEM>>>(pH2 + (size_t)OFF[d - 1] * 160, 10,
                                                  pWhp, 480, pF, 160, nullptr, 10);
        }
        level_kernel<<<(n * 160 + 255) / 256, 256>>>(out, OFF[d], OFF[d - 1], n);
    }

    // 5. levels 4..8: fused fp32 kernels (n = 256, 64, 16, 4, 1)
    for (int d = 4; d <= 8; d++)
        small_level_kernel<<<SIZES[d], 160>>>(out, OFF[d], OFF[d - 1]);
}

// round 15
// speedup vs baseline: 1.4777x; 1.0684x over previous
#include <cuda_runtime.h>
#include <cuda_fp16.h>
#include <cstdint>
#include <math.h>

#define NNODES 87381
#define NLEAF  65536

// =================== scratch (device globals; no allocation) =================
// Tiled half2 layout for GEMM A operands (128-row x 16-col chunks):
//   half2 word(row,k2) = base[(rowblk*NCH + chunk)*1024 + (s*128+m)*4 + c4]
//   chunk=k>>4, kk=k&15, s=kk>>3, c4=(kk&7)>>1; word = (k_even, k_odd).
__device__ __align__(16) __half g_E2[683u * 19 * 2048];  // fp16 embs, tiled
__device__ __align__(16) __half g_X [88064u * 640];      // x-projections [i|u|o|f]
__device__ __align__(16) __half g_H2[683u * 10 * 2048];  // fp16 h, tiled, 160-pad
__device__ __align__(16) __half g_HS2[128u * 10 * 2048]; // fp16 child-sum, tiled
__device__ float  g_C [NNODES * 150];                    // cell states (fp32)
__device__ __align__(16) __half g_P [16384u * 480];      // parent proj [i|u|o]
__device__ __align__(16) __half g_F [65536u * 160];      // child f-projections
// B operands: [chunk][s][c4][col(640)][parity] halves (rows of 1280 halves)
__device__ __align__(16) __half g_Wxp[19 * 10240];       // Wx packed fp16
__device__ __align__(16) __half g_Whp[10 * 10240];       // Wh packed fp16
__device__ float g_Wh2[160 * 640];        // Wh plain fp32 for small levels
__device__ float g_bx[640];
__device__ float g_bh[640];

// =================== helpers ==================================================
__device__ __forceinline__ float sigf(float x) {
    return __fdividef(1.0f, 1.0f + __expf(-x));
}
__device__ __forceinline__ float tanh_fast(float x) {
    return __fdividef(2.0f, 1.0f + __expf(-2.0f * x)) - 1.0f;
}
// half-element index of h(row, j) in tiled buffer (NCH = 10)
__device__ __forceinline__ size_t hpos(int row, int j) {
    int rb = row >> 7, m = row & 127;
    int chunk = j >> 4, kk = j & 15;
    int s = kk >> 3, r = kk & 7;
    return ((size_t)(rb * 10 + chunk) << 11) +
           (size_t)((((s << 7) + m) * 4 + (r >> 1)) * 2 + (r & 1));
}
__device__ __forceinline__ void mma16(float* d, const unsigned* a, const unsigned* b) {
    asm volatile(
        "mma.sync.aligned.m16n8k16.row.col.f32.f16.f16.f32 "
        "{%0,%1,%2,%3}, {%4,%5,%6,%7}, {%8,%9}, {%0,%1,%2,%3};\n"
        : "+f"(d[0]), "+f"(d[1]), "+f"(d[2]), "+f"(d[3])
        : "r"(a[0]), "r"(a[1]), "r"(a[2]), "r"(a[3]), "r"(b[0]), "r"(b[1]));
}
__device__ __forceinline__ void cp16(uint32_t dst, const void* src) {
    asm volatile("cp.async.ca.shared.global [%0], [%1], 16;" :: "r"(dst), "l"(src));
}
#define CP_COMMIT() asm volatile("cp.async.commit_group;" ::: "memory")
#define CP_WAIT2()  asm volatile("cp.async.wait_group 2;" ::: "memory")

// =================== prep: embs->tiled fp16 + weight packing =================
__global__ void prep_kernel(const float* __restrict__ embs,
    const float* Wix, const float* bix, const float* Wfx, const float* bfx,
    const float* Wux, const float* bux, const float* Wox, const float* box_,
    const float* Wih, const float* bih, const float* Wfh, const float* bfh,
    const float* Wuh, const float* buh, const float* Woh, const float* boh)
{
    const int TOTE = 683 * 19 * 1024;   // half2 words of E2
    const int T0 = 19 * 10240;          // Wxp halves
    const int T1 = T0 + 10 * 10240;     // Whp halves
    const int T2 = T1 + 160 * 640;      // Wh2 floats
    const int T3 = T2 + 640;            // bx
    const int T4 = T3 + 640;            // bh
    int idx = blockIdx.x * blockDim.x + threadIdx.x;
    if (idx < TOTE) {
        int w2 = idx & 1023, t = idx >> 10;
        int chunk = t % 19, rb = t / 19;
        int c4 = w2 & 3, m = (w2 >> 2) & 127, s = w2 >> 9;
        int row = (rb << 7) + m;
        int k = chunk * 16 + s * 8 + c4 * 2;
        float vx = 0.f, vy = 0.f;
        if (row < NNODES) {
            const float* er = embs + (size_t)row * 300;
            if (k < 300)     vx = er[k];
            if (k + 1 < 300) vy = er[k + 1];
        }
        ((__half2*)g_E2)[idx] = __floats2half2_rn(vx, vy);
        return;
    }
    int p = idx - TOTE;
    if (p >= T4) return;
    if (p < T0) {
        int rowI = p / 1280, w = p % 1280;
        int col = w >> 1, par = w & 1;
        int chunk = rowI >> 3, rr = rowI & 7;
        int k = chunk * 16 + (rr >> 2) * 8 + (rr & 3) * 2 + par;
        int m = col / 160, cc = col % 160;
        float v = 0.f;
        if (k < 300 && cc < 150) {
            const float* W = (m == 0) ? Wix : (m == 1) ? Wux : (m == 2) ? Wox : Wfx;
            v = W[k * 150 + cc];
        }
        g_Wxp[p] = __float2half_rn(v);
    } else if (p < T1) {
        int t = p - T0;
        int rowI = t / 1280, w = t % 1280;
        int col = w >> 1, par = w & 1;
        int chunk = rowI >> 3, rr = rowI & 7;
        int k = chunk * 16 + (rr >> 2) * 8 + (rr & 3) * 2 + par;
        int m = col / 160, cc = col % 160;
        float v = 0.f;
        if (k < 150 && cc < 150) {
            const float* W = (m == 0) ? Wih : (m == 1) ? Wuh : (m == 2) ? Woh : Wfh;
            v = W[k * 150 + cc];
        }
        g_Whp[t] = __float2half_rn(v);
    } else if (p < T2) {
        int t = p - T1;
        int k = t / 640, c = t % 640, m = c / 160, cc = c % 160;
        float v = 0.f;
        if (k < 150 && cc < 150) {
            const float* W = (m == 0) ? Wih : (m == 1) ? Wuh : (m == 2) ? Woh : Wfh;
            v = W[k * 150 + cc];
        }
        g_Wh2[t] = v;
    } else if (p < T3) {
        int c = p - T2, m = c / 160, cc = c % 160;
        float v = 0.f;
        if (cc < 150) {
            const float* b = (m == 0) ? bix : (m == 1) ? bux : (m == 2) ? box_ : bfx;
            v = b[cc];
        }
        g_bx[c] = v;
    } else {
        int c = p - T3, m = c / 160, cc = c % 160;
        float v = 0.f;
        if (cc < 150) {
            const float* b = (m == 0) ? bih : (m == 1) ? buh : (m == 2) ? boh : bfh;
            v = b[cc];
        }
        g_bh[c] = v;
    }
}

// =================== fp16 mma GEMM body (m16n8k16, 3-stage cp.async) ==========
// BM=128, BN=160, 256 thr = 8 warps (2m x 4n), warp tile 64x40.
// Stage = 9472 B: A 4096 B + B 8 rows x 672 B. All LDS.32 conflict-free.
template<bool BIAS>
__device__ __forceinline__ void gemm_body(
    const __half* __restrict__ At0,   // A2 + rowblk*nch*2048 (tiled rows)
    const __half* __restrict__ Bp, int col0,
    __half* __restrict__ C, int ldc,
    const float* __restrict__ bias,
    int nchunk, int m0, int colblk, char* smb)
{
    const uint32_t sbase = (uint32_t)__cvta_generic_to_shared(smb);
    const int STGB = 9472;

    const int tid    = threadIdx.x;
    const int lane   = tid & 31;
    const int wid    = tid >> 5;
    const int m_warp = (wid >> 2) * 64;
    const int n_warp = (wid & 3) * 40;
    const int bcol0  = col0 + colblk;
    const int c4     = lane & 3;
    const int q      = lane >> 2;

    float acc[4][5][4];
#pragma unroll
    for (int i = 0; i < 4; i++)
#pragma unroll
        for (int j = 0; j < 5; j++)
#pragma unroll
            for (int p = 0; p < 4; p++) acc[i][j][p] = 0.0f;

    auto issue = [&](int st, int ch) {
        if (ch < nchunk) {
            const uint32_t dbase = sbase + st * STGB;
            cp16(dbase + tid * 16, At0 + (size_t)ch * 2048 + tid * 8);
            const __half* Bt = Bp + (size_t)ch * 10240 + (size_t)bcol0 * 2;
#pragma unroll
            for (int e = 0; e < 2; e++) {
                int id = tid + e * 256;
                if (id < 320) {
                    int r = id / 40, o = id - r * 40;
                    cp16(dbase + 4096 + r * 672 + o * 16, Bt + r * 1280 + o * 8);
                }
            }
        }
        CP_COMMIT();
    };

    issue(0, 0);
    issue(1, 1);
    issue(2, 2);

    int st = 0;
    for (int ch = 0; ch < nchunk; ch++) {
        CP_WAIT2();
        __syncthreads();
        const uint32_t* Au = (const uint32_t*)(smb + (size_t)st * STGB);
        const uint32_t* Bu = (const uint32_t*)(smb + (size_t)st * STGB + 4096);

        unsigned b[5][2];
#pragma unroll
        for (int j = 0; j < 5; j++) {
            int col = n_warp + q + 8 * j;
            b[j][0] = Bu[c4 * 168 + col];
            b[j][1] = Bu[(4 + c4) * 168 + col];
        }
#pragma unroll
        for (int i = 0; i < 4; i++) {
            int m1 = m_warp + 16 * i + q;
            unsigned a[4];
            a[0] = Au[m1 * 4 + c4];
            a[1] = Au[(m1 + 8) * 4 + c4];
            a[2] = Au[(128 + m1) * 4 + c4];
            a[3] = Au[(128 + m1 + 8) * 4 + c4];
#pragma unroll
            for (int j = 0; j < 5; j++) mma16(acc[i][j], a, b[j]);
        }
        __syncthreads();
        issue(st, ch + 3);
        st = (st == 2) ? 0 : st + 1;
    }

    const int r0 = m0 + m_warp + q;
    const int cl = n_warp + c4 * 2;
#pragma unroll
    for (int i = 0; i < 4; i++) {
#pragma unroll
        for (int h = 0; h < 2; h++) {
            int r = r0 + 16 * i + 8 * h;
            __half* crow = C + (size_t)r * ldc + colblk;
#pragma unroll
            for (int j = 0; j < 5; j++) {
                int c = cl + 8 * j;
                float v0 = acc[i][j][2 * h], v1 = acc[i][j][2 * h + 1];
                if (BIAS) {
                    v0 += bias[bcol0 + c];
                    v1 += bias[bcol0 + c + 1];
                }
                *(__half2*)(crow + c) = __floats2half2_rn(v0, v1);
            }
        }
    }
}

// ---- X projection, single launch: grid (4, 683); leaf rows skip f-gate ------
__global__ __launch_bounds__(256, 2)
void gemm_x(const __half* __restrict__ A2, const __half* __restrict__ Bp,
            __half* __restrict__ C, const float* __restrict__ bias)
{
    extern __shared__ __align__(16) char smb[];
    const int cb = blockIdx.x, rb = blockIdx.y;
    if (cb == 3 && rb < 512) return;   // leaves don't need the f-gate block
    gemm_body<true>(A2 + (size_t)rb * 19 * 2048, Bp, 0, C, 640, bias,
                    19, rb * 128, cb * 160, smb);
}

// ---- combined P + F GEMM for one level: grid (7, n/128) ---------------------
__global__ __launch_bounds__(256, 2)
void gemm_pf(const __half* __restrict__ Ap, const __half* __restrict__ Af,
             const __half* __restrict__ Bp,
             __half* __restrict__ Cp, __half* __restrict__ Cf)
{
    extern __shared__ __align__(16) char smb[];
    const int x = blockIdx.x, y = blockIdx.y;
    if (x < 3) {
        gemm_body<false>(Ap + (size_t)y * 10 * 2048, Bp, 0, Cp, 480, nullptr,
                         10, y * 128, x * 160, smb);
    } else {
        int rb = y * 4 + (x - 3);
        gemm_body<false>(Af + (size_t)rb * 10 * 2048, Bp, 480, Cf, 160, nullptr,
                         10, rb * 128, 0, smb);
    }
}

// =================== leaves: gates + child-sum fused ===========================
// Thread per (parent pp, j2-pair): 4 sibling leaves -> h, C, out, H2, HS2.
__global__ void leaf_kernel(float* __restrict__ out)
{
    int idx = blockIdx.x * blockDim.x + threadIdx.x;
    if (idx >= 16384 * 80) return;
    int pp = idx / 80, j2 = (idx - pp * 80) * 2;
    if (j2 >= 150) {
        __half2 z = __floats2half2_rn(0.f, 0.f);
#pragma unroll
        for (int s = 0; s < 4; s++)
            *(__half2*)(g_H2 + hpos(4 * pp + s, j2)) = z;
        *(__half2*)(g_HS2 + hpos(pp, j2)) = z;
        return;
    }
    float bi0 = g_bh[j2],       bi1 = g_bh[j2 + 1];
    float bu0 = g_bh[160 + j2], bu1 = g_bh[161 + j2];
    float bo0 = g_bh[320 + j2], bo1 = g_bh[321 + j2];
    float hsx = 0.f, hsy = 0.f;
#pragma unroll
    for (int s = 0; s < 4; s++) {
        int p = 4 * pp + s;
        const __half* Xr = g_X + (size_t)p * 640;
        float2 xi = __half22float2(*(const __half2*)(Xr + j2));
        float2 xu = __half22float2(*(const __half2*)(Xr + 160 + j2));
        float2 xo = __half22float2(*(const __half2*)(Xr + 320 + j2));
        float2 cv, hv;
        {
            float ig = sigf(xi.x + bi0);
            float ug = tanh_fast(xu.x + bu0);
            float og = sigf(xo.x + bo0);
            cv.x = ig * ug;
            hv.x = og * tanh_fast(cv.x);
        }
        {
            float ig = sigf(xi.y + bi1);
            float ug = tanh_fast(xu.y + bu1);
            float og = sigf(xo.y + bo1);
            cv.y = ig * ug;
            hv.y = og * tanh_fast(cv.y);
        }
        *(float2*)(g_C + (size_t)p * 150 + j2) = cv;
        *(float2*)(out + (size_t)p * 150 + j2) = hv;
        __half2 hh = __floats2half2_rn(hv.x, hv.y);
        *(__half2*)(g_H2 + hpos(p, j2)) = hh;
        float2 hr = __half22float2(hh);
        hsx += hr.x;
        hsy += hr.y;
    }
    *(__half2*)(g_HS2 + hpos(pp, j2)) = __floats2half2_rn(hsx, hsy);
}

// =================== internal level: gates + fc + next-level child-sum ========
// Thread per (group pn of 4 siblings, j2-pair). writeHS: emit HS2 for level d+1.
__global__ void level_kernel(float* __restrict__ out, int off_p, int off_c,
                             int n, int writeHS)
{
    int idx = blockIdx.x * blockDim.x + threadIdx.x;
    if (idx >= (n >> 2) * 80) return;
    int pn = idx / 80, j2 = (idx - pn * 80) * 2;
    if (j2 >= 150) {
        __half2 z = __floats2half2_rn(0.f, 0.f);
#pragma unroll
        for (int s = 0; s < 4; s++)
            *(__half2*)(g_H2 + hpos(off_p + 4 * pn + s, j2)) = z;
        if (writeHS) *(__half2*)(g_HS2 + hpos(pn, j2)) = z;
        return;
    }
    float bi0 = g_bh[j2],       bi1 = g_bh[j2 + 1];
    float bu0 = g_bh[160 + j2], bu1 = g_bh[161 + j2];
    float bo0 = g_bh[320 + j2], bo1 = g_bh[321 + j2];
    float bf0 = g_bh[480 + j2], bf1 = g_bh[481 + j2];
    float hsx = 0.f, hsy = 0.f;
#pragma unroll
    for (int s = 0; s < 4; s++) {
        int p = 4 * pn + s;
        int g = off_p + p;
        const __half* Xr = g_X + (size_t)g * 640;
        const __half* Pr = g_P + (size_t)p * 480;
        float2 xi = __half22float2(*(const __half2*)(Xr + j2));
        float2 xu = __half22float2(*(const __half2*)(Xr + 160 + j2));
        float2 xo = __half22float2(*(const __half2*)(Xr + 320 + j2));
        float2 xf = __half22float2(*(const __half2*)(Xr + 480 + j2));
        float2 pi = __half22float2(*(const __half2*)(Pr + j2));
        float2 pu = __half22float2(*(const __half2*)(Pr + 160 + j2));
        float2 po = __half22float2(*(const __half2*)(Pr + 320 + j2));

        float igx = sigf(xi.x + pi.x + bi0);
        float igy = sigf(xi.y + pi.y + bi1);
        float ugx = tanh_fast(xu.x + pu.x + bu0);
        float ugy = tanh_fast(xu.y + pu.y + bu1);
        float ogx = sigf(xo.x + po.x + bo0);
        float ogy = sigf(xo.y + po.y + bo1);
        float xfx = xf.x + bf0;
        float xfy = xf.y + bf1;

        float fcx = 0.f, fcy = 0.f;
#pragma unroll
        for (int k = 0; k < 4; k++) {
            int cl = 4 * p + k;
            float2 fv = __half22float2(*(const __half2*)(g_F + (size_t)cl * 160 + j2));
            float2 cc = *(const float2*)(g_C + (size_t)(off_c + cl) * 150 + j2);
            fcx = fmaf(sigf(xfx + fv.x), cc.x, fcx);
            fcy = fmaf(sigf(xfy + fv.y), cc.y, fcy);
        }
        float cx = fmaf(igx, ugx, fcx);
        float cy = fmaf(igy, ugy, fcy);
        *(float2*)(g_C + (size_t)g * 150 + j2) = make_float2(cx, cy);
        float hx = ogx * tanh_fast(cx);
        float hy = ogy * tanh_fast(cy);
        *(float2*)(out + (size_t)g * 150 + j2) = make_float2(hx, hy);
        __half2 hh = __floats2half2_rn(hx, hy);
        *(__half2*)(g_H2 + hpos(g, j2)) = hh;
        float2 hr = __half22float2(hh);
        hsx += hr.x;
        hsy += hr.y;
    }
    if (writeHS)
        *(__half2*)(g_HS2 + hpos(pn, j2)) = __floats2half2_rn(hsx, hsy);
}

// =================== fused small level (d=4..8, n<=256) ========================
__global__ __launch_bounds__(160)
void small_level_kernel(float* __restrict__ out, int off_p, int off_c)
{
    int p = blockIdx.x, j = threadIdx.x;
    __shared__ float hs[160];
    __shared__ float hch[4][160];
    int g = off_p + p;
    float h0 = __half2float(g_H2[hpos(off_c + 4 * p + 0, j)]);
    float h1 = __half2float(g_H2[hpos(off_c + 4 * p + 1, j)]);
    float h2 = __half2float(g_H2[hpos(off_c + 4 * p + 2, j)]);
    float h3 = __half2float(g_H2[hpos(off_c + 4 * p + 3, j)]);
    hch[0][j] = h0; hch[1][j] = h1; hch[2][j] = h2; hch[3][j] = h3;
    hs[j] = h0 + h1 + h2 + h3;
    __syncthreads();

    float di = 0.f, du = 0.f, dog = 0.f;
    float df0 = 0.f, df1 = 0.f, df2 = 0.f, df3 = 0.f;
#pragma unroll 4
    for (int m = 0; m < 160; m++) {
        float hm = hs[m];
        const float* wrow = g_Wh2 + m * 640;
        di  = fmaf(hm, wrow[j], di);
        du  = fmaf(hm, wrow[160 + j], du);
        dog = fmaf(hm, wrow[320 + j], dog);
        float wf = wrow[480 + j];
        df0 = fmaf(hch[0][m], wf, df0);
        df1 = fmaf(hch[1][m], wf, df1);
        df2 = fmaf(hch[2][m], wf, df2);
        df3 = fmaf(hch[3][m], wf, df3);
    }
    if (j < 150) {
        const __half* Xr = g_X + (size_t)g * 640;
        float ig = sigf(__half2float(Xr[j]) + di + g_bh[j]);
        float ug = tanh_fast(__half2float(Xr[160 + j]) + du + g_bh[160 + j]);
        float og = sigf(__half2float(Xr[320 + j]) + dog + g_bh[320 + j]);
        float xf = __half2float(Xr[480 + j]) + g_bh[480 + j];
        float fc = sigf(xf + df0) * g_C[(size_t)(off_c + 4 * p + 0) * 150 + j]
                 + sigf(xf + df1) * g_C[(size_t)(off_c + 4 * p + 1) * 150 + j]
                 + sigf(xf + df2) * g_C[(size_t)(off_c + 4 * p + 2) * 150 + j]
                 + sigf(xf + df3) * g_C[(size_t)(off_c + 4 * p + 3) * 150 + j];
        float c = fmaf(ig, ug, fc);
        g_C[(size_t)g * 150 + j] = c;
        float h = og * tanh_fast(c);
        out[(size_t)g * 150 + j] = h;
        g_H2[hpos(g, j)] = __float2half_rn(h);
    } else {
        g_H2[hpos(g, j)] = __float2half_rn(0.f);
    }
}

// =================== host orchestration ========================================
extern "C" void kernel_launch(void* const* d_in, const int* in_sizes, int n_in,
                              void* d_out, int out_size)
{
    const float* embs = (const float*)d_in[0];
    const float* Wix = (const float*)d_in[1];  const float* bix = (const float*)d_in[2];
    const float* Wfx = (const float*)d_in[3];  const float* bfx = (const float*)d_in[4];
    const float* Wux = (const float*)d_in[5];  const float* bux = (const float*)d_in[6];
    const float* Wox = (const float*)d_in[7];  const float* box_ = (const float*)d_in[8];
    const float* Wih = (const float*)d_in[9];  const float* bih = (const float*)d_in[10];
    const float* Wfh = (const float*)d_in[11]; const float* bfh = (const float*)d_in[12];
    const float* Wuh = (const float*)d_in[13]; const float* buh = (const float*)d_in[14];
    const float* Woh = (const float*)d_in[15]; const float* boh = (const float*)d_in[16];
    float* out = (float*)d_out;

    __half *pE2, *pX, *pH2, *pHS2, *pWxp, *pWhp, *pP, *pF;
    float *pbx;
    cudaGetSymbolAddress((void**)&pE2,  g_E2);
    cudaGetSymbolAddress((void**)&pX,   g_X);
    cudaGetSymbolAddress((void**)&pH2,  g_H2);
    cudaGetSymbolAddress((void**)&pHS2, g_HS2);
    cudaGetSymbolAddress((void**)&pWxp, g_Wxp);
    cudaGetSymbolAddress((void**)&pWhp, g_Whp);
    cudaGetSymbolAddress((void**)&pbx,  g_bx);
    cudaGetSymbolAddress((void**)&pP,   g_P);
    cudaGetSymbolAddress((void**)&pF,   g_F);

    static const int SIZES[9] = {65536, 16384, 4096, 1024, 256, 64, 16, 4, 1};
    static const int OFF[9]   = {0, 65536, 81920, 86016, 87040, 87296, 87360, 87376, 87380};
    const int SMEM = 3 * 9472;   // 28416 B

    cudaFuncSetAttribute(gemm_x,
                         cudaFuncAttributeMaxDynamicSharedMemorySize, SMEM);
    cudaFuncSetAttribute(gemm_pf,
                         cudaFuncAttributeMaxDynamicSharedMemorySize, SMEM);

    // 1. prep: embs round+tile, weight pack (one launch)
    {
        const int TOT = 683 * 19 * 1024 + (19 * 10240 + 10 * 10240 + 160 * 640 + 1280);
        prep_kernel<<<(TOT + 255) / 256, 256>>>(embs,
            Wix, bix, Wfx, bfx, Wux, bux, Wox, box_,
            Wih, bih, Wfh, bfh, Wuh, buh, Woh, boh);
    }

    // 2. X projections, one launch (leaf row-blocks skip the f-gate column)
    {
        dim3 grid(4, 683);
        gemm_x<<<grid, 256, SMEM>>>(pE2, pWxp, pX, pbx);
    }

    // 3. leaves (+ child-sum for level 1)
    leaf_kernel<<<(16384 * 80 + 255) / 256, 256>>>(out);

    // 4. levels 1..3: one P+F GEMM launch, one level(+hsum) launch each
    for (int d = 1; d <= 3; d++) {
        int n = SIZES[d];
        {
            dim3 grid(7, n / 128);
            gemm_pf<<<grid, 256, SMEM>>>(pHS2, pH2 + (size_t)OFF[d - 1] * 160,
                                         pWhp, pP, pF);
        }
        level_kernel<<<((n >> 2) * 80 + 255) / 256, 256>>>(out, OFF[d], OFF[d - 1],
                                                           n, d < 3 ? 1 : 0);
    }

    // 5. levels 4..8: fused fp32 kernels (n = 256, 64, 16, 4, 1)
    for (int d = 4; d <= 8; d++)
        small_level_kernel<<<SIZES[d], 160>>>(out, OFF[d], OFF[d - 1]);
}